// round 2
// baseline (speedup 1.0000x reference)
#include <cuda_runtime.h>
#include <math.h>

// Problem constants (match reference)
#define NN   50000
#define EE   500000
#define DD   128
#define BB   50
#define NPG  1000
#define KSEL 500
#define BK   (BB*KSEL)   // 25000 selected nodes
#define ALPHA_F 0.6f

// ---------------- scratch (static device globals; no runtime alloc) ----------------
__device__ int   g_deg[NN];
__device__ float g_dinv[NN];
__device__ float g_zs[NN];      // dinv[n] * (x[n] . W_s)
__device__ float g_sf[NN];      // x[n] . W_f + b_f
__device__ float g_ssacc[NN];   // sum of zs[src] into dst
__device__ float g_score[NN];
__device__ int   g_perm[BK];
__device__ int   g_nodemap[NN];
__device__ __align__(16) float g_acc[BK*DD];  // per selected dst: sum of dinv[s]*x[s]
__device__ int   g_bsum[512];
__device__ int   g_boff[512];

// ---------------- init ----------------
__global__ void k_init() {
    int i = blockIdx.x * blockDim.x + threadIdx.x;
    int stride = gridDim.x * blockDim.x;
    float4* acc4 = (float4*)g_acc;
    for (int t = i; t < BK*DD/4; t += stride) acc4[t] = make_float4(0.f,0.f,0.f,0.f);
    for (int t = i; t < NN; t += stride) {
        g_deg[t] = 1;            // self loop
        g_nodemap[t] = -1;
        g_ssacc[t] = 0.f;
    }
}

// ---------------- degree (in-degree at dst, + self loop from init) ----------------
__global__ void k_deg(const int* __restrict__ dst) {
    int e = blockIdx.x * blockDim.x + threadIdx.x;
    if (e < EE) atomicAdd(&g_deg[dst[e]], 1);
}

// ---------------- per-node GEMVs: structure score pre-term + feature score ----------------
__global__ void k_scores(const float* __restrict__ x, const float* __restrict__ Ws,
                         const float* __restrict__ Wf, const float* __restrict__ bf) {
    int warp = (blockIdx.x * blockDim.x + threadIdx.x) >> 5;
    int lane = threadIdx.x & 31;
    if (warp >= NN) return;
    float4 xv = ((const float4*)x)[warp * 32 + lane];
    float4 ws = ((const float4*)Ws)[lane];
    float4 wf = ((const float4*)Wf)[lane];
    float ds = xv.x*ws.x + xv.y*ws.y + xv.z*ws.z + xv.w*ws.w;
    float df = xv.x*wf.x + xv.y*wf.y + xv.z*wf.z + xv.w*wf.w;
    #pragma unroll
    for (int o = 16; o > 0; o >>= 1) {
        ds += __shfl_down_sync(0xffffffffu, ds, o);
        df += __shfl_down_sync(0xffffffffu, df, o);
    }
    if (lane == 0) {
        float dv = rsqrtf(fmaxf((float)g_deg[warp], 1e-12f));
        g_dinv[warp] = dv;
        g_zs[warp]   = dv * ds;
        g_sf[warp]   = df + bf[0];
    }
}

// ---------------- edge pass for structure score ----------------
__global__ void k_edge_score(const int* __restrict__ src, const int* __restrict__ dst) {
    int e = blockIdx.x * blockDim.x + threadIdx.x;
    if (e < EE) atomicAdd(&g_ssacc[dst[e]], g_zs[src[e]]);
}

// ---------------- final fused score ----------------
__global__ void k_score_final(const float* __restrict__ bs) {
    int n = blockIdx.x * blockDim.x + threadIdx.x;
    if (n < NN) {
        float ss = g_dinv[n] * (g_ssacc[n] + g_zs[n]) + bs[0];
        g_score[n] = tanhf(ALPHA_F * ss + (1.0f - ALPHA_F) * g_sf[n]);
    }
}

// ---------------- per-graph top-k via bitonic sort (desc score, asc index tiebreak) ----------------
__global__ void k_topk(const int* __restrict__ batch, float* __restrict__ out,
                       long permOff, long batchOff) {
    __shared__ float sk[1024];
    __shared__ int   si[1024];
    int b = blockIdx.x, tid = threadIdx.x;
    for (int j = tid; j < 1024; j += 512) {
        if (j < NPG) { sk[j] = g_score[b * NPG + j]; si[j] = j; }
        else         { sk[j] = -INFINITY;            si[j] = 1 << 29; }
    }
    __syncthreads();
    for (int k = 2; k <= 1024; k <<= 1) {
        for (int j = k >> 1; j > 0; j >>= 1) {
            int lo = tid & (j - 1);
            int i  = ((tid & ~(j - 1)) << 1) | lo;
            int l  = i | j;
            bool asc = ((i & k) == 0);
            float ka = sk[i], kb = sk[l];
            int   ia = si[i], ib = si[l];
            bool aFirst = (ka > kb) || (ka == kb && ia < ib);
            bool doswap = asc ? !aFirst : aFirst;
            if (doswap) { sk[i] = kb; sk[l] = ka; si[i] = ib; si[l] = ia; }
            __syncthreads();
        }
    }
    if (tid < KSEL) {
        int p  = b * NPG + si[tid];
        int gi = b * KSEL + tid;
        g_perm[gi]   = p;
        g_nodemap[p] = gi;
        out[permOff  + gi] = (float)p;
        out[batchOff + gi] = (float)batch[p];
    }
}

// ---------------- edge feature aggregation into selected dsts (1 warp / edge) ----------------
__global__ void k_edge_feat(const int* __restrict__ src, const int* __restrict__ dst,
                            const float* __restrict__ x) {
    int w    = (blockIdx.x * blockDim.x + threadIdx.x) >> 5;
    int lane = threadIdx.x & 31;
    if (w >= EE) return;
    int d  = dst[w];
    int ci = g_nodemap[d];
    if (ci < 0) return;          // only selected destinations contribute
    int s  = src[w];
    float ds = g_dinv[s];
    float4 xv = ((const float4*)x)[s * 32 + lane];
    float* p = &g_acc[ci * DD + lane * 4];
    asm volatile("red.global.add.v4.f32 [%0], {%1,%2,%3,%4};"
                 :: "l"(p), "f"(ds * xv.x), "f"(ds * xv.y),
                    "f"(ds * xv.z), "f"(ds * xv.w)
                 : "memory");
}

// ---------------- fused prologue + GEMM (25000x128 @ 128x128) + epilogue ----------------
__global__ void __launch_bounds__(256)
k_gemm(const float* __restrict__ x, const float* __restrict__ W,
       const float* __restrict__ bfu, float* __restrict__ out, long xaeOff) {
    __shared__ float sA[64][36];
    __shared__ float sB[32][128];
    __shared__ float sDinv[64];
    __shared__ int   sPerm[64];
    __shared__ float sScore[64];

    int tid  = threadIdx.x;
    int row0 = blockIdx.x * 64;
    if (tid < 64) {
        int r = row0 + tid;
        if (r < BK) {
            int p = g_perm[r];
            sPerm[tid]  = p;
            sDinv[tid]  = g_dinv[p];
            sScore[tid] = g_score[p];
        } else {
            sPerm[tid] = 0; sDinv[tid] = 0.f; sScore[tid] = 0.f;
        }
    }
    __syncthreads();

    float acc[8][4] = {};
    int tx = tid & 31, ty = tid >> 5;

    for (int kk = 0; kk < DD; kk += 32) {
        // sA: normalized aggregated input rows
        for (int q = tid; q < 512; q += 256) {
            int r = q >> 3, k4 = (q & 7) * 4;
            float4 av = make_float4(0.f, 0.f, 0.f, 0.f);
            int grow = row0 + r;
            if (grow < BK) {
                float4 a = *(const float4*)&g_acc[grow * DD + kk + k4];
                float4 xv = *(const float4*)&x[(long)sPerm[r] * DD + kk + k4];
                float dv = sDinv[r];
                av.x = dv * (a.x + dv * xv.x);
                av.y = dv * (a.y + dv * xv.y);
                av.z = dv * (a.z + dv * xv.z);
                av.w = dv * (a.w + dv * xv.w);
            }
            *(float4*)&sA[r][k4] = av;
        }
        // sB: W tile
        for (int q = tid; q < 1024; q += 256) {
            int k = q >> 5, c4 = (q & 31) * 4;
            *(float4*)&sB[k][c4] = *(const float4*)&W[(long)(kk + k) * DD + c4];
        }
        __syncthreads();
        #pragma unroll
        for (int k = 0; k < 32; k++) {
            float4 b4 = *(float4*)&sB[k][tx * 4];
            #pragma unroll
            for (int i = 0; i < 8; i++) {
                float a = sA[ty * 8 + i][k];
                acc[i][0] += a * b4.x;
                acc[i][1] += a * b4.y;
                acc[i][2] += a * b4.z;
                acc[i][3] += a * b4.w;
            }
        }
        __syncthreads();
    }

    float4 bias = *(const float4*)&bfu[tx * 4];
    #pragma unroll
    for (int i = 0; i < 8; i++) {
        int r = ty * 8 + i;
        int grow = row0 + r;
        if (grow < BK) {
            float sc = sScore[r];
            float v0 = acc[i][0] + bias.x;
            float v1 = acc[i][1] + bias.y;
            float v2 = acc[i][2] + bias.z;
            float v3 = acc[i][3] + bias.w;
            long base = (long)grow * DD + tx * 4;
            // x_out region starts at element 0 -> 16B aligned, use float4
            *(float4*)&out[base] = make_float4(v0 * sc, v1 * sc, v2 * sc, v3 * sc);
            // x_ae region offset contains 2*M (M data-dependent, may be odd):
            // only 8B alignment guaranteed -> two float2 stores
            *(float2*)&out[xaeOff + base]     = make_float2(v0, v1);
            *(float2*)&out[xaeOff + base + 2] = make_float2(v2, v3);
        }
    }
}

// ---------------- stable edge compaction ----------------
#define SCAN_T 256
#define SCAN_I 8
#define SCAN_B ((EE + SCAN_T*SCAN_I - 1) / (SCAN_T*SCAN_I))

__global__ void k_flag(const int* __restrict__ src, const int* __restrict__ dst) {
    __shared__ int wsum[8];
    int tid = threadIdx.x;
    int base = blockIdx.x * SCAN_T * SCAN_I + tid * SCAN_I;
    int cnt = 0;
    #pragma unroll
    for (int t = 0; t < SCAN_I; t++) {
        int e = base + t;
        if (e < EE && g_nodemap[src[e]] >= 0 && g_nodemap[dst[e]] >= 0) cnt++;
    }
    int lane = tid & 31, wid = tid >> 5;
    int v = cnt;
    #pragma unroll
    for (int o = 16; o > 0; o >>= 1) v += __shfl_down_sync(0xffffffffu, v, o);
    if (lane == 0) wsum[wid] = v;
    __syncthreads();
    if (tid == 0) {
        int tot = 0;
        for (int w = 0; w < 8; w++) tot += wsum[w];
        g_bsum[blockIdx.x] = tot;
    }
}

__global__ void k_scan() {
    if (threadIdx.x == 0) {
        int run = 0;
        for (int b = 0; b < SCAN_B; b++) { g_boff[b] = run; run += g_bsum[b]; }
    }
}

__global__ void k_scatter(const int* __restrict__ src, const int* __restrict__ dst,
                          float* __restrict__ out, long edgeOff, int M) {
    __shared__ int wsum[8];
    __shared__ int woff[8];
    int tid = threadIdx.x;
    int base = blockIdx.x * SCAN_T * SCAN_I + tid * SCAN_I;
    int f[SCAN_I], r[SCAN_I], c[SCAN_I];
    int cnt = 0;
    #pragma unroll
    for (int t = 0; t < SCAN_I; t++) {
        int e = base + t;
        f[t] = 0;
        if (e < EE) {
            int rr = g_nodemap[src[e]];
            int cc = g_nodemap[dst[e]];
            if (rr >= 0 && cc >= 0) { f[t] = 1; r[t] = rr; c[t] = cc; cnt++; }
        }
    }
    int lane = tid & 31, wid = tid >> 5;
    int v = cnt;
    #pragma unroll
    for (int o = 1; o < 32; o <<= 1) {
        int u = __shfl_up_sync(0xffffffffu, v, o);
        if (lane >= o) v += u;
    }
    if (lane == 31) wsum[wid] = v;
    __syncthreads();
    if (tid == 0) {
        int run = 0;
        for (int w = 0; w < 8; w++) { woff[w] = run; run += wsum[w]; }
    }
    __syncthreads();
    int pos = (v - cnt) + woff[wid] + g_boff[blockIdx.x];
    #pragma unroll
    for (int t = 0; t < SCAN_I; t++) {
        if (f[t]) {
            out[edgeOff + pos]     = (float)r[t];
            out[edgeOff + M + pos] = (float)c[t];
            pos++;
        }
    }
}

// ---------------- launch ----------------
extern "C" void kernel_launch(void* const* d_in, const int* in_sizes, int n_in,
                              void* d_out, int out_size) {
    const float* x    = (const float*)d_in[0];
    const int*   ei   = (const int*)d_in[1];
    const int*   batch= (const int*)d_in[2];
    const float* Ws   = (const float*)d_in[3];
    const float* bs   = (const float*)d_in[4];
    const float* Wf   = (const float*)d_in[5];
    const float* bf   = (const float*)d_in[6];
    const float* Wfu  = (const float*)d_in[7];
    const float* bfu  = (const float*)d_in[8];
    float* out = (float*)d_out;

    const int* src = ei;
    const int* dst = ei + EE;

    long M = ((long)out_size - (2L * BK * DD + 2L * BK)) / 2;
    long edgeOff  = (long)BK * DD;
    long batchOff = edgeOff + 2 * M;
    long permOff  = batchOff + BK;
    long xaeOff   = permOff + BK;

    k_init<<<1024, 256>>>();
    k_deg<<<(EE + 255) / 256, 256>>>(dst);
    k_scores<<<(NN * 32 + 255) / 256, 256>>>(x, Ws, Wf, bf);
    k_edge_score<<<(EE + 255) / 256, 256>>>(src, dst);
    k_score_final<<<(NN + 255) / 256, 256>>>(bs);
    k_topk<<<BB, 512>>>(batch, out, permOff, batchOff);
    k_edge_feat<<<(EE * 32 + 255) / 256, 256>>>(src, dst, x);
    k_gemm<<<(BK + 63) / 64, 256>>>(x, Wfu, bfu, out, xaeOff);
    k_flag<<<SCAN_B, SCAN_T>>>(src, dst);
    k_scan<<<1, 32>>>();
    k_scatter<<<SCAN_B, SCAN_T>>>(src, dst, out, edgeOff, (int)M);
}

// round 3
// speedup vs baseline: 1.3307x; 1.3307x over previous
#include <cuda_runtime.h>
#include <math.h>

// Problem constants (match reference)
#define NN   50000
#define EE   500000
#define DD   128
#define BB   50
#define NPG  1000
#define KSEL 500
#define BK   (BB*KSEL)   // 25000 selected nodes
#define ALPHA_F 0.6f

// ---------------- scratch (static device globals; no runtime alloc) ----------------
__device__ int   g_deg[NN];      // in-degree (no self loop)
__device__ float g_dinv[NN];     // rsqrt(deg+1)
__device__ float g_zs[NN];       // dinv[n] * (x[n] . W_s)
__device__ float g_sf[NN];       // x[n] . W_f + b_f
__device__ float g_score[NN];
__device__ int   g_perm[BK];
__device__ int   g_nodemap[NN];
__device__ __align__(16) float g_acc[BK*DD];  // normalized aggregated rows for selected nodes
__device__ int   g_off[NN];
__device__ int   g_cursor[NN];
__device__ int   g_csr[EE];
__device__ int   g_total;
__device__ int   g_bsum[512];
__device__ int   g_boff[512];

// ---------------- init ----------------
__global__ void k_init() {
    int i = blockIdx.x * blockDim.x + threadIdx.x;
    int stride = gridDim.x * blockDim.x;
    if (i == 0) g_total = 0;
    for (int t = i; t < NN; t += stride) {
        g_deg[t] = 0;
        g_cursor[t] = 0;
        g_nodemap[t] = -1;
    }
}

// ---------------- in-degree histogram ----------------
__global__ void k_deg(const int* __restrict__ dst) {
    int e = blockIdx.x * blockDim.x + threadIdx.x;
    if (e < EE) atomicAdd(&g_deg[dst[e]], 1);
}

// ---------------- offsets (atomic bump; list order is irrelevant) + dinv ----------------
__global__ void k_offsets() {
    int n = blockIdx.x * blockDim.x + threadIdx.x;
    if (n < NN) {
        int d = g_deg[n];
        g_off[n]  = atomicAdd(&g_total, d);
        g_dinv[n] = rsqrtf((float)(d + 1));   // + self loop
    }
}

// ---------------- CSR scatter: in-edge source lists per dst ----------------
__global__ void k_csr(const int* __restrict__ src, const int* __restrict__ dst) {
    int e = blockIdx.x * blockDim.x + threadIdx.x;
    if (e < EE) {
        int d = dst[e];
        int pos = atomicAdd(&g_cursor[d], 1);
        g_csr[g_off[d] + pos] = src[e];
    }
}

// ---------------- per-node GEMVs: structure score pre-term + feature score ----------------
__global__ void k_scores(const float* __restrict__ x, const float* __restrict__ Ws,
                         const float* __restrict__ Wf, const float* __restrict__ bf) {
    int warp = (blockIdx.x * blockDim.x + threadIdx.x) >> 5;
    int lane = threadIdx.x & 31;
    if (warp >= NN) return;
    float4 xv = ((const float4*)x)[warp * 32 + lane];
    float4 ws = ((const float4*)Ws)[lane];
    float4 wf = ((const float4*)Wf)[lane];
    float ds = xv.x*ws.x + xv.y*ws.y + xv.z*ws.z + xv.w*ws.w;
    float df = xv.x*wf.x + xv.y*wf.y + xv.z*wf.z + xv.w*wf.w;
    #pragma unroll
    for (int o = 16; o > 0; o >>= 1) {
        ds += __shfl_down_sync(0xffffffffu, ds, o);
        df += __shfl_down_sync(0xffffffffu, df, o);
    }
    if (lane == 0) {
        g_zs[warp] = g_dinv[warp] * ds;
        g_sf[warp] = df + bf[0];
    }
}

// ---------------- gather-based structure score + fused tanh ----------------
__global__ void k_gather_score(const float* __restrict__ bs) {
    int n = blockIdx.x * blockDim.x + threadIdx.x;
    if (n >= NN) return;
    int beg = g_off[n], len = g_deg[n];
    float sum = g_zs[n];                 // self loop term
    #pragma unroll 4
    for (int i = 0; i < len; i++)
        sum += g_zs[g_csr[beg + i]];
    float ss = g_dinv[n] * sum + bs[0];
    g_score[n] = tanhf(ALPHA_F * ss + (1.0f - ALPHA_F) * g_sf[n]);
}

// ---------------- per-graph top-k via bitonic sort (desc score, asc index tiebreak) ----------------
__global__ void k_topk(const int* __restrict__ batch, float* __restrict__ out,
                       long permOff, long batchOff) {
    __shared__ float sk[1024];
    __shared__ int   si[1024];
    int b = blockIdx.x, tid = threadIdx.x;
    for (int j = tid; j < 1024; j += 512) {
        if (j < NPG) { sk[j] = g_score[b * NPG + j]; si[j] = j; }
        else         { sk[j] = -INFINITY;            si[j] = 1 << 29; }
    }
    __syncthreads();
    for (int k = 2; k <= 1024; k <<= 1) {
        for (int j = k >> 1; j > 0; j >>= 1) {
            int lo = tid & (j - 1);
            int i  = ((tid & ~(j - 1)) << 1) | lo;
            int l  = i | j;
            bool asc = ((i & k) == 0);
            float ka = sk[i], kb = sk[l];
            int   ia = si[i], ib = si[l];
            bool aFirst = (ka > kb) || (ka == kb && ia < ib);
            bool doswap = asc ? !aFirst : aFirst;
            if (doswap) { sk[i] = kb; sk[l] = ka; si[i] = ib; si[l] = ia; }
            __syncthreads();
        }
    }
    if (tid < KSEL) {
        int p  = b * NPG + si[tid];
        int gi = b * KSEL + tid;
        g_perm[gi]   = p;
        g_nodemap[p] = gi;
        out[permOff  + gi] = (float)p;
        out[batchOff + gi] = (float)batch[p];
    }
}

// ---------------- gather-based feature aggregation: one warp per selected node ----------------
// writes fully normalized A row: dinv[p] * ( sum_{s in in(p)} dinv[s]*x[s] + dinv[p]*x[p] )
__global__ void k_gather_feat(const float* __restrict__ x) {
    int r    = (blockIdx.x * blockDim.x + threadIdx.x) >> 5;
    int lane = threadIdx.x & 31;
    if (r >= BK) return;
    int   p   = g_perm[r];
    float dvp = g_dinv[p];
    float4 xv = ((const float4*)x)[p * 32 + lane];
    float4 acc = make_float4(dvp*xv.x, dvp*xv.y, dvp*xv.z, dvp*xv.w);  // self term
    int beg = g_off[p], len = g_deg[p];
    for (int base = 0; base < len; base += 32) {
        int i = base + lane;
        int s  = (i < len) ? g_csr[beg + i] : 0;
        float dv = (i < len) ? g_dinv[s] : 0.f;
        int cnt = min(32, len - base);
        for (int j = 0; j < cnt; j++) {
            int   sj = __shfl_sync(0xffffffffu, s,  j);
            float dj = __shfl_sync(0xffffffffu, dv, j);
            float4 xs = ((const float4*)x)[sj * 32 + lane];
            acc.x += dj * xs.x;
            acc.y += dj * xs.y;
            acc.z += dj * xs.z;
            acc.w += dj * xs.w;
        }
    }
    *(float4*)&g_acc[r * DD + lane * 4] =
        make_float4(dvp*acc.x, dvp*acc.y, dvp*acc.z, dvp*acc.w);
}

// ---------------- GEMM (25000x128 @ 128x128) + bias + score epilogue ----------------
__global__ void __launch_bounds__(256)
k_gemm(const float* __restrict__ W, const float* __restrict__ bfu,
       float* __restrict__ out, long xaeOff) {
    __shared__ float sA[64][36];
    __shared__ float sB[32][128];
    __shared__ float sScore[64];

    int tid  = threadIdx.x;
    int row0 = blockIdx.x * 64;
    if (tid < 64) {
        int r = row0 + tid;
        sScore[tid] = (r < BK) ? g_score[g_perm[r]] : 0.f;
    }
    __syncthreads();

    float acc[8][4] = {};
    int tx = tid & 31, ty = tid >> 5;

    for (int kk = 0; kk < DD; kk += 32) {
        for (int q = tid; q < 512; q += 256) {
            int r = q >> 3, k4 = (q & 7) * 4;
            int grow = row0 + r;
            float4 av = (grow < BK) ? *(const float4*)&g_acc[grow * DD + kk + k4]
                                    : make_float4(0.f, 0.f, 0.f, 0.f);
            *(float4*)&sA[r][k4] = av;
        }
        for (int q = tid; q < 1024; q += 256) {
            int k = q >> 5, c4 = (q & 31) * 4;
            *(float4*)&sB[k][c4] = *(const float4*)&W[(long)(kk + k) * DD + c4];
        }
        __syncthreads();
        #pragma unroll
        for (int k = 0; k < 32; k++) {
            float4 b4 = *(float4*)&sB[k][tx * 4];
            #pragma unroll
            for (int i = 0; i < 8; i++) {
                float a = sA[ty * 8 + i][k];
                acc[i][0] += a * b4.x;
                acc[i][1] += a * b4.y;
                acc[i][2] += a * b4.z;
                acc[i][3] += a * b4.w;
            }
        }
        __syncthreads();
    }

    float4 bias = *(const float4*)&bfu[tx * 4];
    #pragma unroll
    for (int i = 0; i < 8; i++) {
        int r = ty * 8 + i;
        int grow = row0 + r;
        if (grow < BK) {
            float sc = sScore[r];
            float v0 = acc[i][0] + bias.x;
            float v1 = acc[i][1] + bias.y;
            float v2 = acc[i][2] + bias.z;
            float v3 = acc[i][3] + bias.w;
            long base = (long)grow * DD + tx * 4;
            // x_out region starts at element 0 -> 16B aligned
            *(float4*)&out[base] = make_float4(v0*sc, v1*sc, v2*sc, v3*sc);
            // x_ae offset contains 2*M (possibly odd) -> only 8B alignment
            *(float2*)&out[xaeOff + base]     = make_float2(v0, v1);
            *(float2*)&out[xaeOff + base + 2] = make_float2(v2, v3);
        }
    }
}

// ---------------- stable edge compaction ----------------
#define SCAN_T 256
#define SCAN_I 8
#define SCAN_B ((EE + SCAN_T*SCAN_I - 1) / (SCAN_T*SCAN_I))

__global__ void k_flag(const int* __restrict__ src, const int* __restrict__ dst) {
    __shared__ int wsum[8];
    int tid = threadIdx.x;
    int base = blockIdx.x * SCAN_T * SCAN_I + tid * SCAN_I;
    int cnt = 0;
    #pragma unroll
    for (int t = 0; t < SCAN_I; t++) {
        int e = base + t;
        if (e < EE && g_nodemap[src[e]] >= 0 && g_nodemap[dst[e]] >= 0) cnt++;
    }
    int lane = tid & 31, wid = tid >> 5;
    int v = cnt;
    #pragma unroll
    for (int o = 16; o > 0; o >>= 1) v += __shfl_down_sync(0xffffffffu, v, o);
    if (lane == 0) wsum[wid] = v;
    __syncthreads();
    if (tid == 0) {
        int tot = 0;
        for (int w = 0; w < 8; w++) tot += wsum[w];
        g_bsum[blockIdx.x] = tot;
    }
}

__global__ void k_scan() {
    if (threadIdx.x == 0) {
        int run = 0;
        for (int b = 0; b < SCAN_B; b++) { g_boff[b] = run; run += g_bsum[b]; }
    }
}

__global__ void k_scatter(const int* __restrict__ src, const int* __restrict__ dst,
                          float* __restrict__ out, long edgeOff, int M) {
    __shared__ int wsum[8];
    __shared__ int woff[8];
    int tid = threadIdx.x;
    int base = blockIdx.x * SCAN_T * SCAN_I + tid * SCAN_I;
    int f[SCAN_I], r[SCAN_I], c[SCAN_I];
    int cnt = 0;
    #pragma unroll
    for (int t = 0; t < SCAN_I; t++) {
        int e = base + t;
        f[t] = 0;
        if (e < EE) {
            int rr = g_nodemap[src[e]];
            int cc = g_nodemap[dst[e]];
            if (rr >= 0 && cc >= 0) { f[t] = 1; r[t] = rr; c[t] = cc; cnt++; }
        }
    }
    int lane = tid & 31, wid = tid >> 5;
    int v = cnt;
    #pragma unroll
    for (int o = 1; o < 32; o <<= 1) {
        int u = __shfl_up_sync(0xffffffffu, v, o);
        if (lane >= o) v += u;
    }
    if (lane == 31) wsum[wid] = v;
    __syncthreads();
    if (tid == 0) {
        int run = 0;
        for (int w = 0; w < 8; w++) { woff[w] = run; run += wsum[w]; }
    }
    __syncthreads();
    int pos = (v - cnt) + woff[wid] + g_boff[blockIdx.x];
    #pragma unroll
    for (int t = 0; t < SCAN_I; t++) {
        if (f[t]) {
            out[edgeOff + pos]     = (float)r[t];
            out[edgeOff + M + pos] = (float)c[t];
            pos++;
        }
    }
}

// ---------------- launch ----------------
extern "C" void kernel_launch(void* const* d_in, const int* in_sizes, int n_in,
                              void* d_out, int out_size) {
    const float* x    = (const float*)d_in[0];
    const int*   ei   = (const int*)d_in[1];
    const int*   batch= (const int*)d_in[2];
    const float* Ws   = (const float*)d_in[3];
    const float* bs   = (const float*)d_in[4];
    const float* Wf   = (const float*)d_in[5];
    const float* bf   = (const float*)d_in[6];
    const float* Wfu  = (const float*)d_in[7];
    const float* bfu  = (const float*)d_in[8];
    float* out = (float*)d_out;

    const int* src = ei;
    const int* dst = ei + EE;

    long M = ((long)out_size - (2L * BK * DD + 2L * BK)) / 2;
    long edgeOff  = (long)BK * DD;
    long batchOff = edgeOff + 2 * M;
    long permOff  = batchOff + BK;
    long xaeOff   = permOff + BK;

    k_init<<<256, 256>>>();
    k_deg<<<(EE + 255) / 256, 256>>>(dst);
    k_offsets<<<(NN + 255) / 256, 256>>>();
    k_csr<<<(EE + 255) / 256, 256>>>(src, dst);
    k_scores<<<(NN * 32 + 255) / 256, 256>>>(x, Ws, Wf, bf);
    k_gather_score<<<(NN + 255) / 256, 256>>>(bs);
    k_topk<<<BB, 512>>>(batch, out, permOff, batchOff);
    k_gather_feat<<<(BK * 32 + 255) / 256, 256>>>(x);
    k_gemm<<<(BK + 63) / 64, 256>>>(Wfu, bfu, out, xaeOff);
    k_flag<<<SCAN_B, SCAN_T>>>(src, dst);
    k_scan<<<1, 32>>>();
    k_scatter<<<SCAN_B, SCAN_T>>>(src, dst, out, edgeOff, (int)M);
}

// round 4
// speedup vs baseline: 1.6687x; 1.2540x over previous
#include <cuda_runtime.h>
#include <math.h>

// Problem constants (match reference)
#define NN   50000
#define EE   500000
#define DD   128
#define BB   50
#define NPG  1000
#define KSEL 500
#define BK   (BB*KSEL)   // 25000 selected nodes
#define ALPHA_F 0.6f

// ---------------- scratch (static device globals; no runtime alloc) ----------------
__device__ int   g_deg[NN];      // in-degree (no self loop)
__device__ float g_dinv[NN];     // rsqrt(deg+1)
__device__ float g_ds[NN];       // raw x[n].W_s
__device__ float g_zs[NN];       // dinv[n] * ds[n]
__device__ float g_sf[NN];       // x[n].W_f + b_f
__device__ float g_score[NN];
__device__ int   g_perm[BK];
__device__ int   g_nodemap[NN];
__device__ int   g_off[NN];
__device__ int   g_cursor[NN];
__device__ int   g_csr[EE];
__device__ int   g_total;
__device__ int   g_bsum[512];
__device__ int   g_boff[512];

// ---------------- init ----------------
__global__ void k_init() {
    int i = blockIdx.x * blockDim.x + threadIdx.x;
    int stride = gridDim.x * blockDim.x;
    if (i == 0) g_total = 0;
    for (int t = i; t < NN; t += stride) {
        g_deg[t] = 0;
        g_nodemap[t] = -1;
    }
}

// ---------------- in-degree histogram (vec4 edge loads) ----------------
__global__ void k_deg(const int* __restrict__ dst) {
    int i = blockIdx.x * blockDim.x + threadIdx.x;
    if (i < EE / 4) {
        int4 d4 = ((const int4*)dst)[i];
        atomicAdd(&g_deg[d4.x], 1);
        atomicAdd(&g_deg[d4.y], 1);
        atomicAdd(&g_deg[d4.z], 1);
        atomicAdd(&g_deg[d4.w], 1);
    }
}

// ---------------- offsets (atomic bump) + dinv + cursor seed ----------------
__global__ void k_offsets() {
    int n = blockIdx.x * blockDim.x + threadIdx.x;
    if (n < NN) {
        int d = g_deg[n];
        int o = atomicAdd(&g_total, d);
        g_off[n]    = o;
        g_cursor[n] = o;
        g_dinv[n]   = rsqrtf((float)(d + 1));   // + self loop
    }
}

// ---------------- CSR scatter (vec4 edge loads) ----------------
__global__ void k_csr(const int* __restrict__ src, const int* __restrict__ dst) {
    int i = blockIdx.x * blockDim.x + threadIdx.x;
    if (i < EE / 4) {
        int4 s4 = ((const int4*)src)[i];
        int4 d4 = ((const int4*)dst)[i];
        g_csr[atomicAdd(&g_cursor[d4.x], 1)] = s4.x;
        g_csr[atomicAdd(&g_cursor[d4.y], 1)] = s4.y;
        g_csr[atomicAdd(&g_cursor[d4.z], 1)] = s4.z;
        g_csr[atomicAdd(&g_cursor[d4.w], 1)] = s4.w;
    }
}

// ---------------- per-node GEMVs (raw; dinv applied later) ----------------
__global__ void k_scores(const float* __restrict__ x, const float* __restrict__ Ws,
                         const float* __restrict__ Wf, const float* __restrict__ bf) {
    int warp = (blockIdx.x * blockDim.x + threadIdx.x) >> 5;
    int lane = threadIdx.x & 31;
    if (warp >= NN) return;
    float4 xv = ((const float4*)x)[warp * 32 + lane];
    float4 ws = ((const float4*)Ws)[lane];
    float4 wf = ((const float4*)Wf)[lane];
    float ds = xv.x*ws.x + xv.y*ws.y + xv.z*ws.z + xv.w*ws.w;
    float df = xv.x*wf.x + xv.y*wf.y + xv.z*wf.z + xv.w*wf.w;
    #pragma unroll
    for (int o = 16; o > 0; o >>= 1) {
        ds += __shfl_down_sync(0xffffffffu, ds, o);
        df += __shfl_down_sync(0xffffffffu, df, o);
    }
    if (lane == 0) {
        g_ds[warp] = ds;
        g_sf[warp] = df + bf[0];
    }
}

// ---------------- zs = dinv * ds ----------------
__global__ void k_zs() {
    int n = blockIdx.x * blockDim.x + threadIdx.x;
    if (n < NN) g_zs[n] = g_dinv[n] * g_ds[n];
}

// ---------------- gather-based structure score + fused tanh ----------------
__global__ void k_gather_score(const float* __restrict__ bs) {
    int n = blockIdx.x * blockDim.x + threadIdx.x;
    if (n >= NN) return;
    int beg = g_off[n], len = g_deg[n];
    float sum = g_zs[n];                 // self loop term
    #pragma unroll 4
    for (int i = 0; i < len; i++)
        sum += g_zs[g_csr[beg + i]];
    float ss = g_dinv[n] * sum + bs[0];
    g_score[n] = tanhf(ALPHA_F * ss + (1.0f - ALPHA_F) * g_sf[n]);
}

// ---------------- per-graph top-k via bitonic sort (desc score, asc index tiebreak) ----------------
__global__ void k_topk(const int* __restrict__ batch, float* __restrict__ out,
                       long permOff, long batchOff) {
    __shared__ float sk[1024];
    __shared__ int   si[1024];
    int b = blockIdx.x, tid = threadIdx.x;
    for (int j = tid; j < 1024; j += 512) {
        if (j < NPG) { sk[j] = g_score[b * NPG + j]; si[j] = j; }
        else         { sk[j] = -INFINITY;            si[j] = 1 << 29; }
    }
    __syncthreads();
    for (int k = 2; k <= 1024; k <<= 1) {
        for (int j = k >> 1; j > 0; j >>= 1) {
            int lo = tid & (j - 1);
            int i  = ((tid & ~(j - 1)) << 1) | lo;
            int l  = i | j;
            bool asc = ((i & k) == 0);
            float ka = sk[i], kb = sk[l];
            int   ia = si[i], ib = si[l];
            bool aFirst = (ka > kb) || (ka == kb && ia < ib);
            bool doswap = asc ? !aFirst : aFirst;
            if (doswap) { sk[i] = kb; sk[l] = ka; si[i] = ib; si[l] = ia; }
            __syncthreads();
        }
    }
    if (tid < KSEL) {
        int p  = b * NPG + si[tid];
        int gi = b * KSEL + tid;
        g_perm[gi]   = p;
        g_nodemap[p] = gi;
        out[permOff  + gi] = (float)p;
        out[batchOff + gi] = (float)batch[p];
    }
}

// ---------------- fused gather + GEMM (25000x128 @ 128x128) + epilogue ----------------
__global__ void __launch_bounds__(256)
k_gemm(const float* __restrict__ x, const float* __restrict__ W,
       const float* __restrict__ bfu, float* __restrict__ out, long xaeOff) {
    __shared__ float sA[64][128];      // 32 KB: full A rows, gathered
    __shared__ float sB[16][128];      // 8 KB
    __shared__ float sScore[64];

    int tid  = threadIdx.x;
    int lane = tid & 31, wid = tid >> 5;
    int row0 = blockIdx.x * 64;

    if (tid < 64) {
        int r = row0 + tid;
        sScore[tid] = (r < BK) ? g_score[g_perm[r]] : 0.f;
    }

    // gather: warp wid builds rows wid*8 .. wid*8+7
    #pragma unroll
    for (int i = 0; i < 8; i++) {
        int r = wid * 8 + i;
        int grow = row0 + r;
        float4 acc = make_float4(0.f, 0.f, 0.f, 0.f);
        if (grow < BK) {
            int   p   = g_perm[grow];
            float dvp = g_dinv[p];
            float4 xv = ((const float4*)x)[p * 32 + lane];
            acc = make_float4(dvp*xv.x, dvp*xv.y, dvp*xv.z, dvp*xv.w);   // self term
            int beg = g_off[p], len = g_deg[p];
            for (int base = 0; base < len; base += 32) {
                int idx = base + lane;
                int   s  = (idx < len) ? g_csr[beg + idx] : 0;
                float dv = (idx < len) ? g_dinv[s] : 0.f;
                int cnt = min(32, len - base);
                for (int j = 0; j < cnt; j++) {
                    int   sj = __shfl_sync(0xffffffffu, s,  j);
                    float dj = __shfl_sync(0xffffffffu, dv, j);
                    float4 xs = ((const float4*)x)[sj * 32 + lane];
                    acc.x += dj * xs.x;
                    acc.y += dj * xs.y;
                    acc.z += dj * xs.z;
                    acc.w += dj * xs.w;
                }
            }
            acc.x *= dvp; acc.y *= dvp; acc.z *= dvp; acc.w *= dvp;
        }
        *(float4*)&sA[r][lane * 4] = acc;
    }
    __syncthreads();

    float accR[8][4] = {};
    int tx = lane, ty = wid;

    for (int kk = 0; kk < DD; kk += 16) {
        // sB tile: 16x128 = 512 float4s, 2 per thread
        for (int q = tid; q < 512; q += 256) {
            int k = q >> 5, c4 = (q & 31) * 4;
            *(float4*)&sB[k][c4] = *(const float4*)&W[(long)(kk + k) * DD + c4];
        }
        __syncthreads();
        #pragma unroll
        for (int k = 0; k < 16; k++) {
            float4 b4 = *(float4*)&sB[k][tx * 4];
            #pragma unroll
            for (int i = 0; i < 8; i++) {
                float a = sA[ty * 8 + i][kk + k];
                accR[i][0] += a * b4.x;
                accR[i][1] += a * b4.y;
                accR[i][2] += a * b4.z;
                accR[i][3] += a * b4.w;
            }
        }
        __syncthreads();
    }

    float4 bias = *(const float4*)&bfu[tx * 4];
    #pragma unroll
    for (int i = 0; i < 8; i++) {
        int r = ty * 8 + i;
        int grow = row0 + r;
        if (grow < BK) {
            float sc = sScore[r];
            float v0 = accR[i][0] + bias.x;
            float v1 = accR[i][1] + bias.y;
            float v2 = accR[i][2] + bias.z;
            float v3 = accR[i][3] + bias.w;
            long base = (long)grow * DD + tx * 4;
            // x_out region starts at element 0 -> 16B aligned
            *(float4*)&out[base] = make_float4(v0*sc, v1*sc, v2*sc, v3*sc);
            // x_ae offset contains 2*M (possibly odd) -> only 8B alignment
            *(float2*)&out[xaeOff + base]     = make_float2(v0, v1);
            *(float2*)&out[xaeOff + base + 2] = make_float2(v2, v3);
        }
    }
}

// ---------------- stable edge compaction ----------------
#define SCAN_T 256
#define SCAN_I 8
#define SCAN_B ((EE + SCAN_T*SCAN_I - 1) / (SCAN_T*SCAN_I))

__global__ void k_flag(const int* __restrict__ src, const int* __restrict__ dst) {
    __shared__ int wsum[8];
    int tid = threadIdx.x;
    int base = blockIdx.x * SCAN_T * SCAN_I + tid * SCAN_I;
    int cnt = 0;
    #pragma unroll
    for (int t = 0; t < SCAN_I; t++) {
        int e = base + t;
        if (e < EE && g_nodemap[src[e]] >= 0 && g_nodemap[dst[e]] >= 0) cnt++;
    }
    int lane = tid & 31, wid = tid >> 5;
    int v = cnt;
    #pragma unroll
    for (int o = 16; o > 0; o >>= 1) v += __shfl_down_sync(0xffffffffu, v, o);
    if (lane == 0) wsum[wid] = v;
    __syncthreads();
    if (tid == 0) {
        int tot = 0;
        for (int w = 0; w < 8; w++) tot += wsum[w];
        g_bsum[blockIdx.x] = tot;
    }
}

__global__ void k_scan() {
    if (threadIdx.x == 0) {
        int run = 0;
        for (int b = 0; b < SCAN_B; b++) { g_boff[b] = run; run += g_bsum[b]; }
    }
}

__global__ void k_scatter(const int* __restrict__ src, const int* __restrict__ dst,
                          float* __restrict__ out, long edgeOff, int M) {
    __shared__ int wsum[8];
    __shared__ int woff[8];
    int tid = threadIdx.x;
    int base = blockIdx.x * SCAN_T * SCAN_I + tid * SCAN_I;
    int f[SCAN_I], r[SCAN_I], c[SCAN_I];
    int cnt = 0;
    #pragma unroll
    for (int t = 0; t < SCAN_I; t++) {
        int e = base + t;
        f[t] = 0;
        if (e < EE) {
            int rr = g_nodemap[src[e]];
            int cc = g_nodemap[dst[e]];
            if (rr >= 0 && cc >= 0) { f[t] = 1; r[t] = rr; c[t] = cc; cnt++; }
        }
    }
    int lane = tid & 31, wid = tid >> 5;
    int v = cnt;
    #pragma unroll
    for (int o = 1; o < 32; o <<= 1) {
        int u = __shfl_up_sync(0xffffffffu, v, o);
        if (lane >= o) v += u;
    }
    if (lane == 31) wsum[wid] = v;
    __syncthreads();
    if (tid == 0) {
        int run = 0;
        for (int w = 0; w < 8; w++) { woff[w] = run; run += wsum[w]; }
    }
    __syncthreads();
    int pos = (v - cnt) + woff[wid] + g_boff[blockIdx.x];
    #pragma unroll
    for (int t = 0; t < SCAN_I; t++) {
        if (f[t]) {
            out[edgeOff + pos]     = (float)r[t];
            out[edgeOff + M + pos] = (float)c[t];
            pos++;
        }
    }
}

// ---------------- stream/event bundle (created once, outside capture) ----------------
struct AsyncRes {
    cudaStream_t s1, s2;
    cudaEvent_t evRoot, evScores, evTopk, evTail;
    AsyncRes() {
        cudaStreamCreateWithFlags(&s1, cudaStreamNonBlocking);
        cudaStreamCreateWithFlags(&s2, cudaStreamNonBlocking);
        cudaEventCreateWithFlags(&evRoot,   cudaEventDisableTiming);
        cudaEventCreateWithFlags(&evScores, cudaEventDisableTiming);
        cudaEventCreateWithFlags(&evTopk,   cudaEventDisableTiming);
        cudaEventCreateWithFlags(&evTail,   cudaEventDisableTiming);
    }
};

// ---------------- launch ----------------
extern "C" void kernel_launch(void* const* d_in, const int* in_sizes, int n_in,
                              void* d_out, int out_size) {
    const float* x    = (const float*)d_in[0];
    const int*   ei   = (const int*)d_in[1];
    const int*   batch= (const int*)d_in[2];
    const float* Ws   = (const float*)d_in[3];
    const float* bs   = (const float*)d_in[4];
    const float* Wf   = (const float*)d_in[5];
    const float* bf   = (const float*)d_in[6];
    const float* Wfu  = (const float*)d_in[7];
    const float* bfu  = (const float*)d_in[8];
    float* out = (float*)d_out;

    static AsyncRes R;   // constructed on first (non-captured) correctness call

    const int* src = ei;
    const int* dst = ei + EE;

    long M = ((long)out_size - (2L * BK * DD + 2L * BK)) / 2;
    long edgeOff  = (long)BK * DD;
    long batchOff = edgeOff + 2 * M;
    long permOff  = batchOff + BK;
    long xaeOff   = permOff + BK;

    // fork: scores GEMV on s1, independent of CSR build
    cudaEventRecord(R.evRoot, 0);
    cudaStreamWaitEvent(R.s1, R.evRoot, 0);
    k_scores<<<(NN * 32 + 255) / 256, 256, 0, R.s1>>>(x, Ws, Wf, bf);
    cudaEventRecord(R.evScores, R.s1);

    // main: CSR build
    k_init<<<128, 256>>>();
    k_deg<<<(EE / 4 + 255) / 256, 256>>>(dst);
    k_offsets<<<(NN + 255) / 256, 256>>>();
    k_csr<<<(EE / 4 + 255) / 256, 256>>>(src, dst);

    // join scores, then score aggregation + topk
    cudaStreamWaitEvent(0, R.evScores, 0);
    k_zs<<<(NN + 255) / 256, 256>>>();
    k_gather_score<<<(NN + 255) / 256, 256>>>(bs);
    k_topk<<<BB, 512>>>(batch, out, permOff, batchOff);

    // fork: edge compaction on s2 (needs nodemap only)
    cudaEventRecord(R.evTopk, 0);
    cudaStreamWaitEvent(R.s2, R.evTopk, 0);
    k_flag<<<SCAN_B, SCAN_T, 0, R.s2>>>(src, dst);
    k_scan<<<1, 32, 0, R.s2>>>();
    k_scatter<<<SCAN_B, SCAN_T, 0, R.s2>>>(src, dst, out, edgeOff, (int)M);
    cudaEventRecord(R.evTail, R.s2);

    // main: fused gather + GEMM + epilogue
    k_gemm<<<(BK + 63) / 64, 256>>>(x, Wfu, bfu, out, xaeOff);

    // join tail
    cudaStreamWaitEvent(0, R.evTail, 0);
}